// round 5
// baseline (speedup 1.0000x reference)
#include <cuda_runtime.h>

#define B_SZ 4096
#define N_SZ 8192
#define W_SZ 64

// Scratch: __device__ globals (allocation APIs are banned).
__device__ float g_E[(size_t)B_SZ * N_SZ];       // 128 MB: exp(beta*sim)
__device__ float g_mT[W_SZ * N_SZ];              // transposed normalized memory: [w][n]
__device__ float g_kT[W_SZ * B_SZ];              // transposed normalized k * beta: [w][b]

typedef unsigned long long ull;

__device__ __forceinline__ ull pk2(float lo, float hi) {
    ull r; asm("mov.b64 %0, {%1,%2};" : "=l"(r) : "f"(lo), "f"(hi)); return r;
}
__device__ __forceinline__ ull ffma2(ull a, ull b, ull c) {
    ull d; asm("fma.rn.f32x2 %0, %1, %2, %3;" : "=l"(d) : "l"(a), "l"(b), "l"(c)); return d;
}
__device__ __forceinline__ float2 upk2(ull v) {
    float lo, hi; asm("mov.b64 {%0,%1}, %2;" : "=f"(lo), "=f"(hi) : "l"(v));
    return make_float2(lo, hi);
}

// ---------------------------------------------------------------------------
// Kernel 0: row-normalize memory (eps 1e-8) and k (double-normalize per ref,
// eps 1e-12 then 1e-8), fold beta into k rows, and write TRANSPOSED (w-major)
// copies so the GEMM's tile fill is coalesced + bank-conflict-free.
// One warp per row, 2 elements (one float2) per lane.
// ---------------------------------------------------------------------------
__global__ __launch_bounds__(256) void prep_kernel(const float* __restrict__ k,
                                                   const float* __restrict__ mem,
                                                   const float* __restrict__ beta) {
    int gtid = blockIdx.x * blockDim.x + threadIdx.x;
    int warp = gtid >> 5;
    int lane = threadIdx.x & 31;
    if (warp < N_SZ) {
        int n = warp;
        float2 v = ((const float2*)(mem + (size_t)n * W_SZ))[lane];
        float ss = v.x * v.x + v.y * v.y;
        #pragma unroll
        for (int o = 16; o; o >>= 1) ss += __shfl_xor_sync(0xffffffffu, ss, o);
        float inv = 1.0f / fmaxf(sqrtf(ss), 1e-8f);
        g_mT[(size_t)(2 * lane + 0) * N_SZ + n] = v.x * inv;
        g_mT[(size_t)(2 * lane + 1) * N_SZ + n] = v.y * inv;
    } else if (warp < N_SZ + B_SZ) {
        int b = warp - N_SZ;
        float2 v = ((const float2*)(k + (size_t)b * W_SZ))[lane];
        float ss = v.x * v.x + v.y * v.y;
        #pragma unroll
        for (int o = 16; o; o >>= 1) ss += __shfl_xor_sync(0xffffffffu, ss, o);
        float inv1 = 1.0f / fmaxf(sqrtf(ss), 1e-12f);    // F.normalize eps
        float nx = v.x * inv1, ny = v.y * inv1;
        float s2 = nx * nx + ny * ny;
        #pragma unroll
        for (int o = 16; o; o >>= 1) s2 += __shfl_xor_sync(0xffffffffu, s2, o);
        float inv2 = beta[b] / fmaxf(sqrtf(s2), 1e-8f);  // cosine eps; fold beta
        g_kT[(size_t)(2 * lane + 0) * B_SZ + b] = nx * inv2;
        g_kT[(size_t)(2 * lane + 1) * B_SZ + b] = ny * inv2;
    }
}

// ---------------------------------------------------------------------------
// Kernel 1: E[b,n] = exp(dot(kT[:,b], mT[:,n]))  (beta already folded in).
// 64x64 output tile per CTA, K=64 single smem pass. Tiles arrive already
// K-major from g_kT/g_mT: float4 loads, conflict-free STS.128.
// 256 threads as 16x16, 4x4 micro-tile via packed fma.rn.f32x2.
// beta*sim in [-1,1] -> exp without max-subtraction is exact & safe.
// ---------------------------------------------------------------------------
__global__ __launch_bounds__(256) void gemm_exp_kernel() {
    __shared__ __align__(16) float As[W_SZ][68];   // As[w][r] = beta*kC[b0+r][w]
    __shared__ __align__(16) float Bs[W_SZ][68];   // Bs[w][c] = memC[n0+c][w]
    int tid = threadIdx.x;
    int tx = tid & 15, ty = tid >> 4;
    int b0 = blockIdx.y * 64, n0 = blockIdx.x * 64;

    // Tile fill: 1024 float4 per tile. q = r-chunk (low bits -> coalesced
    // global, consecutive smem banks), w = K index.
    #pragma unroll
    for (int i = 0; i < 4; i++) {
        int idx = i * 256 + tid;
        int q = idx & 15;                 // float4 chunk along r/c
        int w = idx >> 4;                 // 0..63
        float4 va = *(const float4*)(g_kT + (size_t)w * B_SZ + b0 + 4 * q);
        *(float4*)&As[w][4 * q] = va;
        float4 vb = *(const float4*)(g_mT + (size_t)w * N_SZ + n0 + 4 * q);
        *(float4*)&Bs[w][4 * q] = vb;
    }
    __syncthreads();

    ull acc[4][2] = {};
    #pragma unroll 16
    for (int kk = 0; kk < W_SZ; kk++) {
        float4 a = *(const float4*)&As[kk][ty * 4];   // broadcast (2 addrs/warp)
        float4 b = *(const float4*)&Bs[kk][tx * 4];   // conflict-free LDS.128
        ull b01 = pk2(b.x, b.y), b23 = pk2(b.z, b.w);
        ull a0 = pk2(a.x, a.x), a1 = pk2(a.y, a.y);
        ull a2 = pk2(a.z, a.z), a3 = pk2(a.w, a.w);
        acc[0][0] = ffma2(a0, b01, acc[0][0]); acc[0][1] = ffma2(a0, b23, acc[0][1]);
        acc[1][0] = ffma2(a1, b01, acc[1][0]); acc[1][1] = ffma2(a1, b23, acc[1][1]);
        acc[2][0] = ffma2(a2, b01, acc[2][0]); acc[2][1] = ffma2(a2, b23, acc[2][1]);
        acc[3][0] = ffma2(a3, b01, acc[3][0]); acc[3][1] = ffma2(a3, b23, acc[3][1]);
    }

    #pragma unroll
    for (int i = 0; i < 4; i++) {
        int r = b0 + ty * 4 + i;
        float2 e01 = upk2(acc[i][0]), e23 = upk2(acc[i][1]);
        float4 ev;
        ev.x = __expf(e01.x); ev.y = __expf(e01.y);
        ev.z = __expf(e23.x); ev.w = __expf(e23.y);
        *(float4*)&g_E[(size_t)r * N_SZ + n0 + tx * 4] = ev;
    }
}

// ---------------------------------------------------------------------------
// Kernel 2: one CTA per row b.
//   pass 1: load E row -> smem (+ row sum), prev -> registers
//   pass 2: gated = (g/rowsum)*E + (1-g)*prev in smem (zero pads)
//   pass 3: 3-tap shift (softmaxed s) + __powf sharpen + block sum
//   pass 4: renormalize, write out
// Rowsum computed locally in fixed tree order -> deterministic, no atomics.
// ---------------------------------------------------------------------------
__global__ __launch_bounds__(256) void finish_kernel(
    const float* __restrict__ g_in, const float* __restrict__ s_in,
    const float* __restrict__ gamma_in, const float* __restrict__ prev,
    float* __restrict__ out)
{
    __shared__ float sg[N_SZ + 2];      // sg[j+1] = value[j]; sg[0]=sg[N+1]=0
    __shared__ float warp_red[8];
    __shared__ float s_bcast;
    int b = blockIdx.x;
    int tid = threadIdx.x;

    float gg = g_in[b];
    float om = 1.0f - gg;
    float s0 = s_in[b * 3 + 0], s1 = s_in[b * 3 + 1], s2 = s_in[b * 3 + 2];
    float mx = fmaxf(s0, fmaxf(s1, s2));
    float w0 = __expf(s0 - mx), w1 = __expf(s1 - mx), w2 = __expf(s2 - mx);
    float wsum = w0 + w1 + w2;
    w0 /= wsum; w1 /= wsum; w2 /= wsum;

    if (tid == 0) { sg[0] = 0.f; sg[N_SZ + 1] = 0.f; }

    // Pass 1: E -> smem, prev -> regs, accumulate row sum of E.
    const float4* E4 = (const float4*)(g_E + (size_t)b * N_SZ);
    const float4* P4 = (const float4*)(prev + (size_t)b * N_SZ);
    float4 p[8];
    float tot = 0.f;
    #pragma unroll
    for (int i = 0; i < 8; i++) {
        int q = i * 256 + tid;
        float4 e = E4[q];
        p[i] = P4[q];
        int j = 4 * q + 1;
        sg[j + 0] = e.x; sg[j + 1] = e.y; sg[j + 2] = e.z; sg[j + 3] = e.w;
        tot += (e.x + e.y) + (e.z + e.w);
    }
    #pragma unroll
    for (int o = 16; o; o >>= 1) tot += __shfl_xor_sync(0xffffffffu, tot, o);
    if ((tid & 31) == 0) warp_red[tid >> 5] = tot;
    __syncthreads();
    if (tid == 0) {
        float t = 0.f;
        #pragma unroll
        for (int w = 0; w < 8; w++) t += warp_red[w];
        s_bcast = t;
    }
    __syncthreads();
    float scale = gg / s_bcast;         // g * softmax normalization

    // Pass 2: gated, each thread overwrites only its own slots.
    #pragma unroll
    for (int i = 0; i < 8; i++) {
        int j = 4 * (i * 256 + tid) + 1;
        sg[j + 0] = scale * sg[j + 0] + om * p[i].x;
        sg[j + 1] = scale * sg[j + 1] + om * p[i].y;
        sg[j + 2] = scale * sg[j + 2] + om * p[i].z;
        sg[j + 3] = scale * sg[j + 3] + om * p[i].w;
    }
    __syncthreads();

    // Pass 3: shift + sharpen + sum.
    float gamma = gamma_in[b];
    float tot2 = 0.f;
    float4 sh[8];
    #pragma unroll
    for (int i = 0; i < 8; i++) {
        int base = 4 * (i * 256 + tid);   // sg index of gated[elem-1]
        float v0 = sg[base + 0], v1 = sg[base + 1], v2 = sg[base + 2];
        float v3 = sg[base + 3], v4 = sg[base + 4], v5 = sg[base + 5];
        float h0 = v0 * w0 + v1 * w1 + v2 * w2;
        float h1 = v1 * w0 + v2 * w1 + v3 * w2;
        float h2 = v2 * w0 + v3 * w1 + v4 * w2;
        float h3 = v3 * w0 + v4 * w1 + v5 * w2;
        h0 = __powf(h0, gamma); h1 = __powf(h1, gamma);
        h2 = __powf(h2, gamma); h3 = __powf(h3, gamma);
        sh[i] = make_float4(h0, h1, h2, h3);
        tot2 += (h0 + h1) + (h2 + h3);
    }
    #pragma unroll
    for (int o = 16; o; o >>= 1) tot2 += __shfl_xor_sync(0xffffffffu, tot2, o);
    __syncthreads();                     // protect warp_red reuse
    if ((tid & 31) == 0) warp_red[tid >> 5] = tot2;
    __syncthreads();
    if (tid == 0) {
        float t = 0.f;
        #pragma unroll
        for (int w = 0; w < 8; w++) t += warp_red[w];
        s_bcast = 1.0f / (t + 1e-8f);
    }
    __syncthreads();
    float inv = s_bcast;

    // Pass 4: write normalized output.
    float4* O4 = (float4*)(out + (size_t)b * N_SZ);
    #pragma unroll
    for (int i = 0; i < 8; i++) {
        int q = i * 256 + tid;
        float4 h = sh[i];
        O4[q] = make_float4(h.x * inv, h.y * inv, h.z * inv, h.w * inv);
    }
}

// ---------------------------------------------------------------------------
// inputs (metadata order): k, beta, g, s, gamma, prev_weights, memory
// ---------------------------------------------------------------------------
extern "C" void kernel_launch(void* const* d_in, const int* in_sizes, int n_in,
                              void* d_out, int out_size) {
    const float* k     = (const float*)d_in[0];
    const float* beta  = (const float*)d_in[1];
    const float* g     = (const float*)d_in[2];
    const float* s     = (const float*)d_in[3];
    const float* gamma = (const float*)d_in[4];
    const float* prev  = (const float*)d_in[5];
    const float* mem   = (const float*)d_in[6];
    float* out = (float*)d_out;

    // 12288 row-warps total (8192 mem + 4096 k) -> 1536 blocks of 256
    prep_kernel<<<1536, 256>>>(k, mem, beta);

    dim3 grid1(N_SZ / 64, B_SZ / 64);   // 128 x 64 CTAs
    gemm_exp_kernel<<<grid1, 256>>>();

    finish_kernel<<<B_SZ, 256>>>(g, s, gamma, prev, out);
}